// round 9
// baseline (speedup 1.0000x reference)
#include <cuda_runtime.h>
#include <cuda_fp16.h>
#include <cstdint>

#define Fq   20
#define Dq   16
#define NBq  500000
#define Bq   4096
#define NIq  190          // F*(F-1)/2
#define NJP  192          // NIq padded
#define FDq  320          // F*D

// Device-global scratch
__device__ __align__(16) float  g_W12[FDq * NJP];   // w1@w2, [k][j] padded
__device__ __align__(16) float  g_W[Bq * NIq];      // z@w1@w2 : [b][j]
__device__ __align__(16) __half g_CT0h[NBq * Dq];   // codebook @ W_top : 16 MB
__device__ __align__(16) __half g_CT1h[NBq * Dq];   // codebook @ W_bot : 16 MB

// ---- fused kernel geometry (192 threads/block) ----
#define CT_TILE_R 192                       // rows per pipeline stage
#define CT_NTILE  4                         // stages per block
#define CT_RPB    (CT_TILE_R * CT_NTILE)    // 768 rows/block
#define CT_BLOCKS ((NBq + CT_RPB - 1) / CT_RPB)   // 652
#define SN_TB     16
#define SN_KC     32
#define SN_BLOCKS (Bq / SN_TB)              // 256

// packed fp32x2 FMA (element-wise, exact fp32 rounding)
union F2U { float2 f; unsigned long long u; };
__device__ __forceinline__ float2 ffma2(float2 a, float2 b, float2 c) {
    F2U A, B, C; A.f = a; B.f = b; C.f = c;
    asm("fma.rn.f32x2 %0, %1, %2, %0;" : "+l"(C.u) : "l"(A.u), "l"(B.u));
    return C.f;
}

__device__ __forceinline__ void cp16(uint32_t s, const void* g) {
    asm volatile("cp.async.cg.shared.global [%0], [%1], 16;" :: "r"(s), "l"(g));
}
__device__ __forceinline__ void cp_commit() {
    asm volatile("cp.async.commit_group;");
}
template <int N> __device__ __forceinline__ void cp_wait() {
    asm volatile("cp.async.wait_group %0;" :: "n"(N));
}

// ---------------------------------------------------------------------------
// K1: W12 = w1 @ w2  (320x320x190), 60 tiles of 32x32, 2x2 per thread.
// ---------------------------------------------------------------------------
__global__ __launch_bounds__(256) void k_w12(
    const float* __restrict__ w1, const float* __restrict__ w2)
{
    __shared__ float As[32][33];
    __shared__ float Bs[32][33];
    const int tile = blockIdx.x;
    const int ti = tile / 6, tj = tile % 6;
    const int row0 = ti * 32, col0 = tj * 32;
    const int tid = threadIdx.x;
    const int tx = tid & 15, ty = tid >> 4;
    float a00 = 0.f, a01 = 0.f, a10 = 0.f, a11 = 0.f;
    for (int k0 = 0; k0 < FDq; k0 += 32) {
        #pragma unroll
        for (int i = tid; i < 32 * 32; i += 256) {
            int r = i >> 5, c = i & 31;
            As[r][c] = w1[(row0 + r) * FDq + k0 + c];
            int cb = col0 + c;
            Bs[r][c] = (cb < NIq) ? w2[(k0 + r) * NIq + cb] : 0.f;
        }
        __syncthreads();
        #pragma unroll
        for (int k = 0; k < 32; k++) {
            float x0 = As[ty * 2][k],  x1 = As[ty * 2 + 1][k];
            float y0 = Bs[k][tx * 2],  y1 = Bs[k][tx * 2 + 1];
            a00 += x0 * y0; a01 += x0 * y1;
            a10 += x1 * y0; a11 += x1 * y1;
        }
        __syncthreads();
    }
    int i0 = row0 + ty * 2, j0 = col0 + tx * 2;
    g_W12[ i0      * NJP + j0    ] = a00;
    g_W12[ i0      * NJP + j0 + 1] = a01;
    g_W12[(i0 + 1) * NJP + j0    ] = a10;
    g_W12[(i0 + 1) * NJP + j0 + 1] = a11;
}

// ---------------------------------------------------------------------------
// K2 (fused, grid-split, 192 threads):
//   blocks [0, CT_BLOCKS): codebook transform -> fp16 tables.
//     cp.async double-buffered staging (no regs), W k-pairs in registers.
//   blocks [CT_BLOCKS, +256): SeNet GEMM g_W = Z @ W12 (4 cols x 4 batches
//     per thread, 2 LDS.128 + 8 FFMA2 per k).
// ---------------------------------------------------------------------------
__global__ __launch_bounds__(192) void k_fused(
    const float* __restrict__ Wt,        // (32,16)
    const float* __restrict__ codebook,  // (500000,16)
    const float* __restrict__ z)         // (B, 320)
{
    __shared__ union {
        struct { float zsT[FDq * SN_TB]; float wsm[SN_KC * NJP]; } sen;  // 45 KB
        float csm[2][CT_TILE_R * 16];                                    // 24 KB
    } sm;

    const int tid = threadIdx.x;

    if (blockIdx.x < CT_BLOCKS) {
        // =========== codebook transform ===========
        const int dg  = tid & 15;       // d-group: 2 output cols
        const int rs  = tid >> 4;       // row slot 0..11
        const int tbl = dg >> 3;        // 0 -> CT0, 1 -> CT1
        const int dd  = (dg & 7) * 2;

        float2 wA[8], wB[8];
        #pragma unroll
        for (int m = 0; m < 8; m++) {
            const float* wr0 = Wt + (tbl * 16 + 2 * m)     * 16;
            const float* wr1 = Wt + (tbl * 16 + 2 * m + 1) * 16;
            wA[m] = make_float2(wr0[dd],     wr1[dd]);
            wB[m] = make_float2(wr0[dd + 1], wr1[dd + 1]);
        }

        __half* ct = tbl ? g_CT1h : g_CT0h;
        const long base = (long)blockIdx.x * CT_RPB;
        const float4* cb4 = (const float4*)codebook;

        // stage tile t into buffer buf (768 float4, coalesced, clamped)
        auto stage = [&](int t, int buf) {
            #pragma unroll
            for (int q = 0; q < 4; q++) {
                int  i = q * 192 + tid;                 // float4 idx in tile
                long r = base + (long)t * CT_TILE_R + (i >> 2);
                long ri = (r < NBq) ? r : (NBq - 1);
                uint32_t s = (uint32_t)__cvta_generic_to_shared(&sm.csm[buf][i * 4]);
                cp16(s, &cb4[ri * 4 + (i & 3)]);
            }
            cp_commit();
        };

        stage(0, 0);
        for (int t = 0; t < CT_NTILE; t++) {
            if (t + 1 < CT_NTILE) { stage(t + 1, (t + 1) & 1); cp_wait<1>(); }
            else                  { cp_wait<0>(); }
            __syncthreads();
            const float* buf = sm.csm[t & 1];
            const long tile0 = base + (long)t * CT_TILE_R;
            #pragma unroll
            for (int rr = 0; rr < 16; rr++) {
                int  lr = rs + rr * 12;
                long r  = tile0 + lr;
                if (r >= NBq) continue;
                const float2* cp = (const float2*)(buf + lr * 16);
                float2 sA = make_float2(0.f, 0.f);
                float2 sB = make_float2(0.f, 0.f);
                #pragma unroll
                for (int m = 0; m < 8; m++) {
                    float2 cc = cp[m];                // LDS.64 broadcast
                    sA = ffma2(cc, wA[m], sA);
                    sB = ffma2(cc, wB[m], sB);
                }
                *(__half2*)(ct + r * Dq + dd) =
                    __floats2half2_rn(sA.x + sA.y, sB.x + sB.y);
            }
            __syncthreads();    // compute done before next stage overwrites
        }
    } else {
        // =========== SeNet GEMM ===========
        float* zsT = sm.sen.zsT;
        float* wsm = sm.sen.wsm;
        const int b0 = (blockIdx.x - CT_BLOCKS) * SN_TB;

        {   // stage z transposed: [k][b]
            const float4* src = (const float4*)(z + b0 * FDq);
            for (int i = tid; i < SN_TB * FDq / 4; i += 192) {
                float4 v = src[i];
                int e = i * 4;
                int b = e / FDq;
                int k = e - b * FDq;
                zsT[ k      * SN_TB + b] = v.x;
                zsT[(k + 1) * SN_TB + b] = v.y;
                zsT[(k + 2) * SN_TB + b] = v.z;
                zsT[(k + 3) * SN_TB + b] = v.w;
            }
        }

        const int bg = tid & 3;
        const int jg = tid >> 2;
        float2 acc[4][2];
        #pragma unroll
        for (int jj = 0; jj < 4; jj++) {
            acc[jj][0] = make_float2(0.f, 0.f);
            acc[jj][1] = make_float2(0.f, 0.f);
        }

        for (int kc = 0; kc < FDq; kc += SN_KC) {
            __syncthreads();
            const float4* wsrc = (const float4*)(g_W12 + kc * NJP);
            for (int i = tid; i < SN_KC * NJP / 4; i += 192)
                ((float4*)wsm)[i] = wsrc[i];
            __syncthreads();
            #pragma unroll 4
            for (int k = 0; k < SN_KC; k++) {
                float4 w4 = *(const float4*)(wsm + k * NJP + jg * 4);
                float4 z4 = *(const float4*)(zsT + (kc + k) * SN_TB + bg * 4);
                float2 z01 = make_float2(z4.x, z4.y);
                float2 z23 = make_float2(z4.z, z4.w);
                acc[0][0] = ffma2(z01, make_float2(w4.x, w4.x), acc[0][0]);
                acc[0][1] = ffma2(z23, make_float2(w4.x, w4.x), acc[0][1]);
                acc[1][0] = ffma2(z01, make_float2(w4.y, w4.y), acc[1][0]);
                acc[1][1] = ffma2(z23, make_float2(w4.y, w4.y), acc[1][1]);
                acc[2][0] = ffma2(z01, make_float2(w4.z, w4.z), acc[2][0]);
                acc[2][1] = ffma2(z23, make_float2(w4.z, w4.z), acc[2][1]);
                acc[3][0] = ffma2(z01, make_float2(w4.w, w4.w), acc[3][0]);
                acc[3][1] = ffma2(z23, make_float2(w4.w, w4.w), acc[3][1]);
            }
        }
        #pragma unroll
        for (int jj = 0; jj < 4; jj++) {
            int j = jg * 4 + jj;
            if (j < NIq) {
                int b = b0 + bg * 4;
                g_W[ b      * NIq + j] = acc[jj][0].x;
                g_W[(b + 1) * NIq + j] = acc[jj][0].y;
                g_W[(b + 2) * NIq + j] = acc[jj][1].x;
                g_W[(b + 3) * NIq + j] = acc[jj][1].y;
            }
        }
    }
}

// ---------------------------------------------------------------------------
// K3: combine, fp16 gathers with explicit MLP=6. 2 batches/block.
// ---------------------------------------------------------------------------
#define BPB 2
#define P1_ITEMS (BPB * NIq * 2)     // 760
__global__ __launch_bounds__(256) void k_combine(
    const int* __restrict__ hash_idx,    // (2, B, NI)
    const int* __restrict__ inter,       // (20, 19)
    float*     __restrict__ out)         // (B, 20, 16)
{
    __shared__ float ws[BPB * NIq];
    __shared__ __align__(16) float embw[BPB][NIq * 20];
    __shared__ int idxs[Fq * (Fq - 1)];
    __shared__ int hs0[BPB * NIq];
    __shared__ int hs1[BPB * NIq];

    const int b0  = blockIdx.x * BPB;
    const int tid = threadIdx.x;

    for (int i = tid; i < BPB * NIq; i += 256) {
        int bb = i / NIq, j = i - bb * NIq;
        ws[i]  = g_W[(b0 + bb) * NIq + j];
        hs0[i] = hash_idx[(b0 + bb) * NIq + j];
        hs1[i] = hash_idx[Bq * NIq + (b0 + bb) * NIq + j];
    }
    for (int i = tid; i < Fq * (Fq - 1); i += 256) idxs[i] = inter[i];
    __syncthreads();

    // phase 1: 3 slots/thread, all 6 gathers issued before any convert
    uint4 av[3], cv[3];
    float wv[3];
    int jjv[3], qv[3];
    bool val[3];
    #pragma unroll
    for (int s = 0; s < 3; s++) {
        int t = tid + s * 256;
        val[s] = (t < P1_ITEMS);
        if (val[s]) {
            int jj = t >> 1, q = t & 1;
            jjv[s] = jj; qv[s] = q;
            av[s] = *(const uint4*)(g_CT0h + hs0[jj] * Dq + q * 8);
            cv[s] = *(const uint4*)(g_CT1h + hs1[jj] * Dq + q * 8);
            wv[s] = ws[jj];
        }
    }
    #pragma unroll
    for (int s = 0; s < 3; s++) {
        if (!val[s]) continue;
        float w = wv[s];
        float2 fa, fc;
        float o[8];
        fa = __half22float2(*(__half2*)&av[s].x); fc = __half22float2(*(__half2*)&cv[s].x);
        o[0] = (fa.x + fc.x) * w; o[1] = (fa.y + fc.y) * w;
        fa = __half22float2(*(__half2*)&av[s].y); fc = __half22float2(*(__half2*)&cv[s].y);
        o[2] = (fa.x + fc.x) * w; o[3] = (fa.y + fc.y) * w;
        fa = __half22float2(*(__half2*)&av[s].z); fc = __half22float2(*(__half2*)&cv[s].z);
        o[4] = (fa.x + fc.x) * w; o[5] = (fa.y + fc.y) * w;
        fa = __half22float2(*(__half2*)&av[s].w); fc = __half22float2(*(__half2*)&cv[s].w);
        o[6] = (fa.x + fc.x) * w; o[7] = (fa.y + fc.y) * w;
        int bb = jjv[s] / NIq, j = jjv[s] - bb * NIq;
        float* dst = &embw[bb][j * 20 + qv[s] * 8];
        *(float4*)dst       = make_float4(o[0], o[1], o[2], o[3]);
        *(float4*)(dst + 4) = make_float4(o[4], o[5], o[6], o[7]);
    }
    __syncthreads();

    #pragma unroll 2
    for (int o = tid; o < BPB * Fq * Dq; o += 256) {
        int bb = o / (Fq * Dq);
        int oo = o - bb * (Fq * Dq);
        int f = oo >> 4, d = oo & 15;
        const int* row = idxs + f * (Fq - 1);
        float s = 0.f;
        #pragma unroll
        for (int p = 0; p < Fq - 1; p++)
            s += embw[bb][row[p] * 20 + d];
        out[(b0 + bb) * Fq * Dq + oo] = s;
    }
}

// ---------------------------------------------------------------------------
extern "C" void kernel_launch(void* const* d_in, const int* in_sizes, int n_in,
                              void* d_out, int out_size) {
    const float* origin   = (const float*)d_in[0];  // (B, F, D)
    const float* codebook = (const float*)d_in[1];  // (NB, D)
    const float* Wt       = (const float*)d_in[2];  // (32, 16)
    const float* w1       = (const float*)d_in[3];  // (320, 320)
    const float* w2       = (const float*)d_in[4];  // (320, 190)
    const int*   hash     = (const int*)d_in[5];    // (2, B, NI)
    const int*   inter    = (const int*)d_in[6];    // (20, 19)
    float*       out      = (float*)d_out;

    k_w12<<<60, 256>>>(w1, w2);
    k_fused<<<CT_BLOCKS + SN_BLOCKS, 192>>>(Wt, codebook, origin);
    k_combine<<<Bq / BPB, 256>>>(hash, inter, out);
}

// round 10
// speedup vs baseline: 1.4177x; 1.4177x over previous
#include <cuda_runtime.h>
#include <cuda_fp16.h>
#include <cstdint>

#define Fq   20
#define Dq   16
#define NBq  500000
#define Bq   4096
#define NIq  190          // F*(F-1)/2
#define NJP  192          // NIq padded
#define FDq  320          // F*D

// Device-global scratch
__device__ __align__(16) float  g_W12[FDq * NJP];   // w1@w2, [k][j] padded
__device__ __align__(16) float  g_W[Bq * NIq];      // z@w1@w2 : [b][j]
__device__ __align__(16) __half g_CT0h[NBq * Dq];   // codebook @ W_top : 16 MB
__device__ __align__(16) __half g_CT1h[NBq * Dq];   // codebook @ W_bot : 16 MB

#define W12_TILES 60                        // 10 x 6 tiles of 32x32
#define CT_TILE   256                       // rows per pipeline stage
#define CT_NTILE  4                         // stages per block (1024 rows)
#define CT_RPB    (CT_TILE * CT_NTILE)
#define CT_BLOCKS ((NBq + CT_RPB - 1) / CT_RPB)   // 489

// packed fp32x2 FMA (element-wise, exact fp32 rounding)
union F2U { float2 f; unsigned long long u; };
__device__ __forceinline__ float2 ffma2(float2 a, float2 b, float2 c) {
    F2U A, B, C; A.f = a; B.f = b; C.f = c;
    asm("fma.rn.f32x2 %0, %1, %2, %0;" : "+l"(C.u) : "l"(A.u), "l"(B.u));
    return C.f;
}

__device__ __forceinline__ void cp16(uint32_t s, const void* g) {
    asm volatile("cp.async.cg.shared.global [%0], [%1], 16;" :: "r"(s), "l"(g));
}
__device__ __forceinline__ void cp_commit() {
    asm volatile("cp.async.commit_group;");
}
template <int N> __device__ __forceinline__ void cp_wait() {
    asm volatile("cp.async.wait_group %0;" :: "n"(N));
}

// ---------------------------------------------------------------------------
// K1 (fused, grid-split, 256 threads):
//   blocks [0,60):  tiled GEMM  g_W12 = w1 @ w2   (hidden under the CT wave)
//   blocks [60,..): codebook transform -> fp16 CT0/CT1.
//     cp.async double-buffered staging (no prefetch registers), W k-pairs in
//     registers, inner loop = LDS.64 broadcast + FFMA2.
// ---------------------------------------------------------------------------
__global__ __launch_bounds__(256) void k_pre(
    const float* __restrict__ w1,        // (320,320)
    const float* __restrict__ w2,        // (320,190)
    const float* __restrict__ Wt,        // (32,16)
    const float* __restrict__ codebook)  // (500000,16)
{
    __shared__ union {
        struct { float As[32][33]; float Bs[32][33]; } gemm;   // 8.4 KB
        float csm[2][CT_TILE * 16];                            // 32 KB
    } sm;

    const int tid = threadIdx.x;

    if (blockIdx.x < W12_TILES) {
        auto& As = sm.gemm.As;
        auto& Bs = sm.gemm.Bs;
        const int tile = blockIdx.x;
        const int ti = tile / 6, tj = tile % 6;
        const int row0 = ti * 32, col0 = tj * 32;
        const int tx = tid & 15, ty = tid >> 4;
        float a00 = 0.f, a01 = 0.f, a10 = 0.f, a11 = 0.f;
        for (int k0 = 0; k0 < FDq; k0 += 32) {
            #pragma unroll
            for (int i = tid; i < 32 * 32; i += 256) {
                int r = i >> 5, c = i & 31;
                As[r][c] = w1[(row0 + r) * FDq + k0 + c];
                int cb = col0 + c;
                Bs[r][c] = (cb < NIq) ? w2[(k0 + r) * NIq + cb] : 0.f;
            }
            __syncthreads();
            #pragma unroll
            for (int k = 0; k < 32; k++) {
                float x0 = As[ty * 2][k],  x1 = As[ty * 2 + 1][k];
                float y0 = Bs[k][tx * 2],  y1 = Bs[k][tx * 2 + 1];
                a00 += x0 * y0; a01 += x0 * y1;
                a10 += x1 * y0; a11 += x1 * y1;
            }
            __syncthreads();
        }
        int i0 = row0 + ty * 2, j0 = col0 + tx * 2;
        g_W12[ i0      * NJP + j0    ] = a00;
        g_W12[ i0      * NJP + j0 + 1] = a01;
        g_W12[(i0 + 1) * NJP + j0    ] = a10;
        g_W12[(i0 + 1) * NJP + j0 + 1] = a11;
    } else {
        const int dg  = tid & 15;       // d-group: 2 output cols
        const int rs  = tid >> 4;       // row slot 0..15
        const int tbl = dg >> 3;        // 0 -> CT0, 1 -> CT1
        const int dd  = (dg & 7) * 2;   // output cols dd, dd+1

        // Preload W k-pairs once (32 regs).
        float2 wA[8], wB[8];
        #pragma unroll
        for (int m = 0; m < 8; m++) {
            const float* wr0 = Wt + (tbl * 16 + 2 * m)     * 16;
            const float* wr1 = Wt + (tbl * 16 + 2 * m + 1) * 16;
            wA[m] = make_float2(wr0[dd],     wr1[dd]);
            wB[m] = make_float2(wr0[dd + 1], wr1[dd + 1]);
        }

        __half* ct = tbl ? g_CT1h : g_CT0h;
        const long base = (long)(blockIdx.x - W12_TILES) * CT_RPB;
        const float4* cb4 = (const float4*)codebook;

        // stage tile t into buffer buf: 1024 float4, coalesced, clamped
        auto stage = [&](int t, int buf) {
            #pragma unroll
            for (int q = 0; q < 4; q++) {
                int  i = q * 256 + tid;                  // float4 idx in tile
                long r = base + (long)t * CT_TILE + (i >> 2);
                long ri = (r < NBq) ? r : (NBq - 1);
                uint32_t s = (uint32_t)__cvta_generic_to_shared(&sm.csm[buf][i * 4]);
                cp16(s, &cb4[ri * 4 + (i & 3)]);
            }
            cp_commit();
        };

        stage(0, 0);
        for (int t = 0; t < CT_NTILE; t++) {
            if (t + 1 < CT_NTILE) { stage(t + 1, (t + 1) & 1); cp_wait<1>(); }
            else                  { cp_wait<0>(); }
            __syncthreads();
            const float* buf = sm.csm[t & 1];
            const long tile0 = base + (long)t * CT_TILE;
            #pragma unroll
            for (int rr = 0; rr < 16; rr++) {
                int  lr = rs + rr * 16;
                long r  = tile0 + lr;
                if (r >= NBq) continue;
                const float2* cp = (const float2*)(buf + lr * 16);
                float2 sA = make_float2(0.f, 0.f);
                float2 sB = make_float2(0.f, 0.f);
                #pragma unroll
                for (int m = 0; m < 8; m++) {
                    float2 cc = cp[m];                // LDS.64 broadcast
                    sA = ffma2(cc, wA[m], sA);
                    sB = ffma2(cc, wB[m], sB);
                }
                *(__half2*)(ct + r * Dq + dd) =
                    __floats2half2_rn(sA.x + sA.y, sB.x + sB.y);
            }
            __syncthreads();    // reads done before next stage overwrites
        }
    }
}

// ---------------------------------------------------------------------------
// K2: g_W = Z @ W12.  256 blocks x 16 batches x 192 cols.
// Thread = 4 cols x 4 batches. Per k: 2 LDS.128 + 8 FFMA2 (4:1 math:load).
// ---------------------------------------------------------------------------
#define SN_TB 16
#define SN_NT 192
#define SN_KC 32
__global__ __launch_bounds__(SN_NT) void k_senet(const float* __restrict__ z) {
    __shared__ __align__(16) float zsT[FDq * SN_TB];     // [k][b] 20 KB
    __shared__ __align__(16) float wsm[SN_KC * NJP];     // 24.6 KB
    const int b0  = blockIdx.x * SN_TB;
    const int tid = threadIdx.x;

    {   // stage z transposed: [k][b]
        const float4* src = (const float4*)(z + b0 * FDq);
        for (int i = tid; i < SN_TB * FDq / 4; i += SN_NT) {
            float4 v = src[i];
            int e = i * 4;
            int b = e / FDq;
            int k = e - b * FDq;
            zsT[ k      * SN_TB + b] = v.x;
            zsT[(k + 1) * SN_TB + b] = v.y;
            zsT[(k + 2) * SN_TB + b] = v.z;
            zsT[(k + 3) * SN_TB + b] = v.w;
        }
    }

    const int bg = tid & 3;        // batch quad
    const int jg = tid >> 2;       // col quad 0..47
    float2 acc[4][2];              // [col][batch-pair]
    #pragma unroll
    for (int jj = 0; jj < 4; jj++) {
        acc[jj][0] = make_float2(0.f, 0.f);
        acc[jj][1] = make_float2(0.f, 0.f);
    }

    for (int kc = 0; kc < FDq; kc += SN_KC) {
        __syncthreads();                       // covers zsT on first iter
        const float4* wsrc = (const float4*)(g_W12 + kc * NJP);
        for (int i = tid; i < SN_KC * NJP / 4; i += SN_NT)
            ((float4*)wsm)[i] = wsrc[i];
        __syncthreads();
        #pragma unroll 4
        for (int k = 0; k < SN_KC; k++) {
            float4 w4 = *(const float4*)(wsm + k * NJP + jg * 4);          // LDS.128
            float4 z4 = *(const float4*)(zsT + (kc + k) * SN_TB + bg * 4); // LDS.128
            float2 z01 = make_float2(z4.x, z4.y);
            float2 z23 = make_float2(z4.z, z4.w);
            acc[0][0] = ffma2(z01, make_float2(w4.x, w4.x), acc[0][0]);
            acc[0][1] = ffma2(z23, make_float2(w4.x, w4.x), acc[0][1]);
            acc[1][0] = ffma2(z01, make_float2(w4.y, w4.y), acc[1][0]);
            acc[1][1] = ffma2(z23, make_float2(w4.y, w4.y), acc[1][1]);
            acc[2][0] = ffma2(z01, make_float2(w4.z, w4.z), acc[2][0]);
            acc[2][1] = ffma2(z23, make_float2(w4.z, w4.z), acc[2][1]);
            acc[3][0] = ffma2(z01, make_float2(w4.w, w4.w), acc[3][0]);
            acc[3][1] = ffma2(z23, make_float2(w4.w, w4.w), acc[3][1]);
        }
    }
    #pragma unroll
    for (int jj = 0; jj < 4; jj++) {
        int j = jg * 4 + jj;
        if (j < NIq) {
            int b = b0 + bg * 4;
            g_W[ b      * NIq + j] = acc[jj][0].x;
            g_W[(b + 1) * NIq + j] = acc[jj][0].y;
            g_W[(b + 2) * NIq + j] = acc[jj][1].x;
            g_W[(b + 3) * NIq + j] = acc[jj][1].y;
        }
    }
}

// ---------------------------------------------------------------------------
// K3: combine, fp16 gathers with explicit MLP=6. 2 batches/block.
// ---------------------------------------------------------------------------
#define BPB 2
#define P1_ITEMS (BPB * NIq * 2)     // 760
__global__ __launch_bounds__(256) void k_combine(
    const int* __restrict__ hash_idx,    // (2, B, NI)
    const int* __restrict__ inter,       // (20, 19)
    float*     __restrict__ out)         // (B, 20, 16)
{
    __shared__ float ws[BPB * NIq];
    __shared__ __align__(16) float embw[BPB][NIq * 20];
    __shared__ int idxs[Fq * (Fq - 1)];
    __shared__ int hs0[BPB * NIq];
    __shared__ int hs1[BPB * NIq];

    const int b0  = blockIdx.x * BPB;
    const int tid = threadIdx.x;

    for (int i = tid; i < BPB * NIq; i += 256) {
        int bb = i / NIq, j = i - bb * NIq;
        ws[i]  = g_W[(b0 + bb) * NIq + j];
        hs0[i] = hash_idx[(b0 + bb) * NIq + j];
        hs1[i] = hash_idx[Bq * NIq + (b0 + bb) * NIq + j];
    }
    for (int i = tid; i < Fq * (Fq - 1); i += 256) idxs[i] = inter[i];
    __syncthreads();

    // phase 1: 3 slots/thread, all 6 gathers issued before any convert
    uint4 av[3], cv[3];
    float wv[3];
    int jjv[3], qv[3];
    bool val[3];
    #pragma unroll
    for (int s = 0; s < 3; s++) {
        int t = tid + s * 256;
        val[s] = (t < P1_ITEMS);
        if (val[s]) {
            int jj = t >> 1, q = t & 1;
            jjv[s] = jj; qv[s] = q;
            av[s] = *(const uint4*)(g_CT0h + hs0[jj] * Dq + q * 8);
            cv[s] = *(const uint4*)(g_CT1h + hs1[jj] * Dq + q * 8);
            wv[s] = ws[jj];
        }
    }
    #pragma unroll
    for (int s = 0; s < 3; s++) {
        if (!val[s]) continue;
        float w = wv[s];
        float2 fa, fc;
        float o[8];
        fa = __half22float2(*(__half2*)&av[s].x); fc = __half22float2(*(__half2*)&cv[s].x);
        o[0] = (fa.x + fc.x) * w; o[1] = (fa.y + fc.y) * w;
        fa = __half22float2(*(__half2*)&av[s].y); fc = __half22float2(*(__half2*)&cv[s].y);
        o[2] = (fa.x + fc.x) * w; o[3] = (fa.y + fc.y) * w;
        fa = __half22float2(*(__half2*)&av[s].z); fc = __half22float2(*(__half2*)&cv[s].z);
        o[4] = (fa.x + fc.x) * w; o[5] = (fa.y + fc.y) * w;
        fa = __half22float2(*(__half2*)&av[s].w); fc = __half22float2(*(__half2*)&cv[s].w);
        o[6] = (fa.x + fc.x) * w; o[7] = (fa.y + fc.y) * w;
        int bb = jjv[s] / NIq, j = jjv[s] - bb * NIq;
        float* dst = &embw[bb][j * 20 + qv[s] * 8];
        *(float4*)dst       = make_float4(o[0], o[1], o[2], o[3]);
        *(float4*)(dst + 4) = make_float4(o[4], o[5], o[6], o[7]);
    }
    __syncthreads();

    #pragma unroll 2
    for (int o = tid; o < BPB * Fq * Dq; o += 256) {
        int bb = o / (Fq * Dq);
        int oo = o - bb * (Fq * Dq);
        int f = oo >> 4, d = oo & 15;
        const int* row = idxs + f * (Fq - 1);
        float s = 0.f;
        #pragma unroll
        for (int p = 0; p < Fq - 1; p++)
            s += embw[bb][row[p] * 20 + d];
        out[(b0 + bb) * Fq * Dq + oo] = s;
    }
}

// ---------------------------------------------------------------------------
extern "C" void kernel_launch(void* const* d_in, const int* in_sizes, int n_in,
                              void* d_out, int out_size) {
    const float* origin   = (const float*)d_in[0];  // (B, F, D)
    const float* codebook = (const float*)d_in[1];  // (NB, D)
    const float* Wt       = (const float*)d_in[2];  // (32, 16)
    const float* w1       = (const float*)d_in[3];  // (320, 320)
    const float* w2       = (const float*)d_in[4];  // (320, 190)
    const int*   hash     = (const int*)d_in[5];    // (2, B, NI)
    const int*   inter    = (const int*)d_in[6];    // (20, 19)
    float*       out      = (float*)d_out;

    k_pre<<<W12_TILES + CT_BLOCKS, 256>>>(w1, w2, Wt, codebook);
    k_senet<<<Bq / SN_TB, SN_NT>>>(origin);
    k_combine<<<Bq / BPB, 256>>>(hash, inter, out);
}

// round 11
// speedup vs baseline: 1.4609x; 1.0304x over previous
#include <cuda_runtime.h>
#include <cuda_fp16.h>
#include <cstdint>

#define Fq   20
#define Dq   16
#define NBq  500000
#define Bq   4096
#define NIq  190          // F*(F-1)/2
#define NJP  192          // NIq padded
#define FDq  320          // F*D

// Device-global scratch
__device__ __align__(16) float  g_W12[FDq * NJP];   // w1@w2, [k][j] padded
__device__ __align__(16) float  g_W[Bq * NIq];      // z@w1@w2 : [b][j]
__device__ __align__(16) __half g_CT0h[NBq * Dq];   // codebook @ W_top : 16 MB
__device__ __align__(16) __half g_CT1h[NBq * Dq];   // codebook @ W_bot : 16 MB

#define W12_TILES 60                        // 10 x 6 tiles of 32x32
#define CT_TILE   256                       // rows per pipeline stage
#define CT_NTILE  2                         // stages per block (512 rows)
#define CT_RPB    (CT_TILE * CT_NTILE)
#define CT_BLOCKS ((NBq + CT_RPB - 1) / CT_RPB)   // 977

// packed fp32x2 FMA (element-wise, exact fp32 rounding)
union F2U { float2 f; unsigned long long u; };
__device__ __forceinline__ float2 ffma2(float2 a, float2 b, float2 c) {
    F2U A, B, C; A.f = a; B.f = b; C.f = c;
    asm("fma.rn.f32x2 %0, %1, %2, %0;" : "+l"(C.u) : "l"(A.u), "l"(B.u));
    return C.f;
}

__device__ __forceinline__ void cp16(uint32_t s, const void* g) {
    asm volatile("cp.async.cg.shared.global [%0], [%1], 16;" :: "r"(s), "l"(g));
}
__device__ __forceinline__ void cp_commit() {
    asm volatile("cp.async.commit_group;");
}
template <int N> __device__ __forceinline__ void cp_wait() {
    asm volatile("cp.async.wait_group %0;" :: "n"(N));
}

// ---------------------------------------------------------------------------
// K1 (fused, grid-split, 256 threads):
//   blocks [0,60):  tiled GEMM  g_W12 = w1 @ w2   (hidden under the CT wave)
//   blocks [60,..): codebook transform -> fp16 CT0/CT1.
//     cp.async double-buffered staging; codebook row read as 4x LDS.128.
// ---------------------------------------------------------------------------
__global__ __launch_bounds__(256) void k_pre(
    const float* __restrict__ w1,        // (320,320)
    const float* __restrict__ w2,        // (320,190)
    const float* __restrict__ Wt,        // (32,16)
    const float* __restrict__ codebook)  // (500000,16)
{
    __shared__ union {
        struct { float As[32][33]; float Bs[32][33]; } gemm;   // 8.4 KB
        float csm[2][CT_TILE * 16];                            // 32 KB
    } sm;

    const int tid = threadIdx.x;

    if (blockIdx.x < W12_TILES) {
        auto& As = sm.gemm.As;
        auto& Bs = sm.gemm.Bs;
        const int tile = blockIdx.x;
        const int ti = tile / 6, tj = tile % 6;
        const int row0 = ti * 32, col0 = tj * 32;
        const int tx = tid & 15, ty = tid >> 4;
        float a00 = 0.f, a01 = 0.f, a10 = 0.f, a11 = 0.f;
        for (int k0 = 0; k0 < FDq; k0 += 32) {
            #pragma unroll
            for (int i = tid; i < 32 * 32; i += 256) {
                int r = i >> 5, c = i & 31;
                As[r][c] = w1[(row0 + r) * FDq + k0 + c];
                int cb = col0 + c;
                Bs[r][c] = (cb < NIq) ? w2[(k0 + r) * NIq + cb] : 0.f;
            }
            __syncthreads();
            #pragma unroll
            for (int k = 0; k < 32; k++) {
                float x0 = As[ty * 2][k],  x1 = As[ty * 2 + 1][k];
                float y0 = Bs[k][tx * 2],  y1 = Bs[k][tx * 2 + 1];
                a00 += x0 * y0; a01 += x0 * y1;
                a10 += x1 * y0; a11 += x1 * y1;
            }
            __syncthreads();
        }
        int i0 = row0 + ty * 2, j0 = col0 + tx * 2;
        g_W12[ i0      * NJP + j0    ] = a00;
        g_W12[ i0      * NJP + j0 + 1] = a01;
        g_W12[(i0 + 1) * NJP + j0    ] = a10;
        g_W12[(i0 + 1) * NJP + j0 + 1] = a11;
    } else {
        const int dg  = tid & 15;       // d-group: 2 output cols
        const int rs  = tid >> 4;       // row slot 0..15
        const int tbl = dg >> 3;        // 0 -> CT0, 1 -> CT1
        const int dd  = (dg & 7) * 2;   // output cols dd, dd+1

        // Preload W k-pairs once (32 regs).
        float2 wA[8], wB[8];
        #pragma unroll
        for (int m = 0; m < 8; m++) {
            const float* wr0 = Wt + (tbl * 16 + 2 * m)     * 16;
            const float* wr1 = Wt + (tbl * 16 + 2 * m + 1) * 16;
            wA[m] = make_float2(wr0[dd],     wr1[dd]);
            wB[m] = make_float2(wr0[dd + 1], wr1[dd + 1]);
        }

        __half* ct = tbl ? g_CT1h : g_CT0h;
        const long base = (long)(blockIdx.x - W12_TILES) * CT_RPB;
        const float4* cb4 = (const float4*)codebook;

        // stage tile t into buffer buf: 1024 float4, coalesced, clamped
        auto stage = [&](int t, int buf) {
            #pragma unroll
            for (int q = 0; q < 4; q++) {
                int  i = q * 256 + tid;                  // float4 idx in tile
                long r = base + (long)t * CT_TILE + (i >> 2);
                long ri = (r < NBq) ? r : (NBq - 1);
                uint32_t s = (uint32_t)__cvta_generic_to_shared(&sm.csm[buf][i * 4]);
                cp16(s, &cb4[ri * 4 + (i & 3)]);
            }
            cp_commit();
        };

        stage(0, 0);
        for (int t = 0; t < CT_NTILE; t++) {
            if (t + 1 < CT_NTILE) { stage(t + 1, (t + 1) & 1); cp_wait<1>(); }
            else                  { cp_wait<0>(); }
            __syncthreads();
            const float* buf = sm.csm[t & 1];
            const long tile0 = base + (long)t * CT_TILE;
            #pragma unroll
            for (int rr = 0; rr < 16; rr++) {
                int  lr = rs + rr * 16;
                long r  = tile0 + lr;
                if (r >= NBq) continue;
                const float4* cp4 = (const float4*)(buf + lr * 16);
                float2 sA = make_float2(0.f, 0.f);
                float2 sB = make_float2(0.f, 0.f);
                #pragma unroll
                for (int m = 0; m < 4; m++) {
                    float4 v = cp4[m];                   // LDS.128 broadcast
                    float2 c01 = make_float2(v.x, v.y);
                    float2 c23 = make_float2(v.z, v.w);
                    sA = ffma2(c01, wA[2 * m],     sA);
                    sB = ffma2(c01, wB[2 * m],     sB);
                    sA = ffma2(c23, wA[2 * m + 1], sA);
                    sB = ffma2(c23, wB[2 * m + 1], sB);
                }
                *(__half2*)(ct + r * Dq + dd) =
                    __floats2half2_rn(sA.x + sA.y, sB.x + sB.y);
            }
            __syncthreads();    // reads done before next stage overwrites
        }
    }
}

// ---------------------------------------------------------------------------
// K2: g_W = Z @ W12.  256 blocks x 16 batches x 192 cols.
// zsT padded to stride 20 (kills 16-way STS conflicts in the transpose stage).
// ---------------------------------------------------------------------------
#define SN_TB 16
#define SN_ZS 20                 // padded batch stride
#define SN_NT 192
#define SN_KC 32
__global__ __launch_bounds__(SN_NT) void k_senet(const float* __restrict__ z) {
    __shared__ __align__(16) float zsT[FDq * SN_ZS];     // [k][b pad 20] 25.6 KB
    __shared__ __align__(16) float wsm[SN_KC * NJP];     // 24.6 KB
    const int b0  = blockIdx.x * SN_TB;
    const int tid = threadIdx.x;

    {   // stage z transposed: [k][b]
        const float4* src = (const float4*)(z + b0 * FDq);
        for (int i = tid; i < SN_TB * FDq / 4; i += SN_NT) {
            float4 v = src[i];
            int e = i * 4;
            int b = e / FDq;
            int k = e - b * FDq;
            zsT[ k      * SN_ZS + b] = v.x;
            zsT[(k + 1) * SN_ZS + b] = v.y;
            zsT[(k + 2) * SN_ZS + b] = v.z;
            zsT[(k + 3) * SN_ZS + b] = v.w;
        }
    }

    const int bg = tid & 3;        // batch quad
    const int jg = tid >> 2;       // col quad 0..47
    float2 acc[4][2];              // [col][batch-pair]
    #pragma unroll
    for (int jj = 0; jj < 4; jj++) {
        acc[jj][0] = make_float2(0.f, 0.f);
        acc[jj][1] = make_float2(0.f, 0.f);
    }

    for (int kc = 0; kc < FDq; kc += SN_KC) {
        __syncthreads();                       // covers zsT on first iter
        const float4* wsrc = (const float4*)(g_W12 + kc * NJP);
        for (int i = tid; i < SN_KC * NJP / 4; i += SN_NT)
            ((float4*)wsm)[i] = wsrc[i];
        __syncthreads();
        #pragma unroll 4
        for (int k = 0; k < SN_KC; k++) {
            float4 w4 = *(const float4*)(wsm + k * NJP + jg * 4);           // LDS.128
            float4 z4 = *(const float4*)(zsT + (kc + k) * SN_ZS + bg * 4);  // LDS.128
            float2 z01 = make_float2(z4.x, z4.y);
            float2 z23 = make_float2(z4.z, z4.w);
            acc[0][0] = ffma2(z01, make_float2(w4.x, w4.x), acc[0][0]);
            acc[0][1] = ffma2(z23, make_float2(w4.x, w4.x), acc[0][1]);
            acc[1][0] = ffma2(z01, make_float2(w4.y, w4.y), acc[1][0]);
            acc[1][1] = ffma2(z23, make_float2(w4.y, w4.y), acc[1][1]);
            acc[2][0] = ffma2(z01, make_float2(w4.z, w4.z), acc[2][0]);
            acc[2][1] = ffma2(z23, make_float2(w4.z, w4.z), acc[2][1]);
            acc[3][0] = ffma2(z01, make_float2(w4.w, w4.w), acc[3][0]);
            acc[3][1] = ffma2(z23, make_float2(w4.w, w4.w), acc[3][1]);
        }
    }
    #pragma unroll
    for (int jj = 0; jj < 4; jj++) {
        int j = jg * 4 + jj;
        if (j < NIq) {
            int b = b0 + bg * 4;
            g_W[ b      * NIq + j] = acc[jj][0].x;
            g_W[(b + 1) * NIq + j] = acc[jj][0].y;
            g_W[(b + 2) * NIq + j] = acc[jj][1].x;
            g_W[(b + 3) * NIq + j] = acc[jj][1].y;
        }
    }
}

// ---------------------------------------------------------------------------
// K3: combine, fp16 gathers with explicit MLP=6. 2 batches/block.
// ---------------------------------------------------------------------------
#define BPB 2
#define P1_ITEMS (BPB * NIq * 2)     // 760
__global__ __launch_bounds__(256) void k_combine(
    const int* __restrict__ hash_idx,    // (2, B, NI)
    const int* __restrict__ inter,       // (20, 19)
    float*     __restrict__ out)         // (B, 20, 16)
{
    __shared__ float ws[BPB * NIq];
    __shared__ __align__(16) float embw[BPB][NIq * 20];
    __shared__ int idxs[Fq * (Fq - 1)];
    __shared__ int hs0[BPB * NIq];
    __shared__ int hs1[BPB * NIq];

    const int b0  = blockIdx.x * BPB;
    const int tid = threadIdx.x;

    for (int i = tid; i < BPB * NIq; i += 256) {
        int bb = i / NIq, j = i - bb * NIq;
        ws[i]  = g_W[(b0 + bb) * NIq + j];
        hs0[i] = hash_idx[(b0 + bb) * NIq + j];
        hs1[i] = hash_idx[Bq * NIq + (b0 + bb) * NIq + j];
    }
    for (int i = tid; i < Fq * (Fq - 1); i += 256) idxs[i] = inter[i];
    __syncthreads();

    // phase 1: 3 slots/thread, all 6 gathers issued before any convert
    uint4 av[3], cv[3];
    float wv[3];
    int jjv[3], qv[3];
    bool val[3];
    #pragma unroll
    for (int s = 0; s < 3; s++) {
        int t = tid + s * 256;
        val[s] = (t < P1_ITEMS);
        if (val[s]) {
            int jj = t >> 1, q = t & 1;
            jjv[s] = jj; qv[s] = q;
            av[s] = *(const uint4*)(g_CT0h + hs0[jj] * Dq + q * 8);
            cv[s] = *(const uint4*)(g_CT1h + hs1[jj] * Dq + q * 8);
            wv[s] = ws[jj];
        }
    }
    #pragma unroll
    for (int s = 0; s < 3; s++) {
        if (!val[s]) continue;
        float w = wv[s];
        float2 fa, fc;
        float o[8];
        fa = __half22float2(*(__half2*)&av[s].x); fc = __half22float2(*(__half2*)&cv[s].x);
        o[0] = (fa.x + fc.x) * w; o[1] = (fa.y + fc.y) * w;
        fa = __half22float2(*(__half2*)&av[s].y); fc = __half22float2(*(__half2*)&cv[s].y);
        o[2] = (fa.x + fc.x) * w; o[3] = (fa.y + fc.y) * w;
        fa = __half22float2(*(__half2*)&av[s].z); fc = __half22float2(*(__half2*)&cv[s].z);
        o[4] = (fa.x + fc.x) * w; o[5] = (fa.y + fc.y) * w;
        fa = __half22float2(*(__half2*)&av[s].w); fc = __half22float2(*(__half2*)&cv[s].w);
        o[6] = (fa.x + fc.x) * w; o[7] = (fa.y + fc.y) * w;
        int bb = jjv[s] / NIq, j = jjv[s] - bb * NIq;
        float* dst = &embw[bb][j * 20 + qv[s] * 8];
        *(float4*)dst       = make_float4(o[0], o[1], o[2], o[3]);
        *(float4*)(dst + 4) = make_float4(o[4], o[5], o[6], o[7]);
    }
    __syncthreads();

    #pragma unroll 2
    for (int o = tid; o < BPB * Fq * Dq; o += 256) {
        int bb = o / (Fq * Dq);
        int oo = o - bb * (Fq * Dq);
        int f = oo >> 4, d = oo & 15;
        const int* row = idxs + f * (Fq - 1);
        float s = 0.f;
        #pragma unroll
        for (int p = 0; p < Fq - 1; p++)
            s += embw[bb][row[p] * 20 + d];
        out[(b0 + bb) * Fq * Dq + oo] = s;
    }
}

// ---------------------------------------------------------------------------
extern "C" void kernel_launch(void* const* d_in, const int* in_sizes, int n_in,
                              void* d_out, int out_size) {
    const float* origin   = (const float*)d_in[0];  // (B, F, D)
    const float* codebook = (const float*)d_in[1];  // (NB, D)
    const float* Wt       = (const float*)d_in[2];  // (32, 16)
    const float* w1       = (const float*)d_in[3];  // (320, 320)
    const float* w2       = (const float*)d_in[4];  // (320, 190)
    const int*   hash     = (const int*)d_in[5];    // (2, B, NI)
    const int*   inter    = (const int*)d_in[6];    // (20, 19)
    float*       out      = (float*)d_out;

    k_pre<<<W12_TILES + CT_BLOCKS, 256>>>(w1, w2, Wt, codebook);
    k_senet<<<Bq / SN_TB, SN_NT>>>(origin);
    k_combine<<<Bq / BPB, 256>>>(hash, inter, out);
}